// round 15
// baseline (speedup 1.0000x reference)
#include <cuda_runtime.h>
#include <cuda_fp16.h>
#include <cstdint>

#define N_NODES 50000
#define N_EDGES 1600000
#define IN_DIM 256
#define OUT_DIM 32
#define NH 4
#define ODIM 128   // NH*OUT_DIM
#define ALPHA 0.2f
#define CAP 128    // slots per node; P(deg>=128) ~ e^-41 per node (Poisson, mean 32)

// ---------------- scratch (no allocations allowed) ----------------
__device__ __half g_hph[N_NODES * ODIM];     // h_prime in fp16 (12.8 MB)
__device__ float4 g_alphas[N_NODES];         // alpha_src per node, 4 heads
__device__ float4 g_alphad[N_NODES];         // alpha_dst per node, 4 heads
__device__ int    g_cursor[N_NODES];         // bucket fill counters (agg resets -> replay-safe)
__device__ int    g_slots[N_NODES * CAP];    // per-dst src buckets (25.6 MB)
__device__ __half g_Whi[IN_DIM * ODIM];      // fp16 split of W (hi)
__device__ __half g_Wlo[IN_DIM * ODIM];      // fp16 split of W (lo)

// ---------------- W split: W = Whi + Wlo (fp16 pair) ----------------
__global__ __launch_bounds__(256) void wsplit_kernel(const float* __restrict__ W) {
    int i = blockIdx.x * blockDim.x + threadIdx.x;
    if (i < IN_DIM * ODIM) {
        float w = W[i];
        __half hi = __float2half(w);
        g_Whi[i] = hi;
        g_Wlo[i] = __float2half(w - __half2float(hi));
    }
}

// ---------------- MMA helpers ----------------
__device__ __forceinline__ uint32_t s2u(const void* p) {
    return (uint32_t)__cvta_generic_to_shared(p);
}
#define LDMX4(r0, r1, r2, r3, addr) \
    asm volatile("ldmatrix.sync.aligned.m8n8.x4.shared.b16 {%0,%1,%2,%3}, [%4];" \
                 : "=r"(r0), "=r"(r1), "=r"(r2), "=r"(r3) : "r"(addr))
#define LDMX4T(r0, r1, r2, r3, addr) \
    asm volatile("ldmatrix.sync.aligned.m8n8.x4.trans.shared.b16 {%0,%1,%2,%3}, [%4];" \
                 : "=r"(r0), "=r"(r1), "=r"(r2), "=r"(r3) : "r"(addr))
#define MMA16816(c, a, b0, b1) \
    asm volatile("mma.sync.aligned.m16n8k16.row.col.f32.f16.f16.f32 " \
                 "{%0,%1,%2,%3}, {%4,%5,%6,%7}, {%8,%9}, {%0,%1,%2,%3};" \
                 : "+f"((c)[0]), "+f"((c)[1]), "+f"((c)[2]), "+f"((c)[3]) \
                 : "r"((a)[0]), "r"((a)[1]), "r"((a)[2]), "r"((a)[3]), \
                   "r"(b0), "r"(b1))

__device__ __forceinline__ void split_f32(float v, __half& hi, __half& lo) {
    hi = __float2half(v);
    lo = __float2half(v - __half2float(hi));
}

// ---------------- GEMM: split-fp16 HMMA, 64 rows x 128 cols per block ----------------
#define TM 64
#define KC 32
#define SA_STR 40    // A smem row stride (halfs): conflict-free ldmatrix
#define SB_STR 136   // B smem row stride (halfs): conflict-free ldmatrix
#define ST_STR 133   // fp32 staging stride: gcd(133,32)=1

__global__ __launch_bounds__(128) void gemm_kernel(const float* __restrict__ h,
                                                   const float* __restrict__ a) {
    __shared__ __align__(16) unsigned char smem_raw[64 * ST_STR * 4];  // 34048 B
    __shared__ float s_asc[ODIM], s_adc[ODIM];

    __half* sa_hi = (__half*)smem_raw;                       // 64*40 halfs
    __half* sa_lo = sa_hi + TM * SA_STR;
    __half* sb_hi = (__half*)(smem_raw + 2 * TM * SA_STR * 2);
    __half* sb_lo = sb_hi + KC * SB_STR;
    float*  st    = (float*)smem_raw;                        // reused after mainloop

    int t = threadIdx.x;
    int w = t >> 5;
    int l = t & 31;
    int block_m = blockIdx.x * TM;

    if (t < ODIM) {
        s_asc[t] = a[(t & 31) * 4 + (t >> 5)];
        s_adc[t] = a[((t & 31) + 32) * 4 + (t >> 5)];
    }

    float acc[16][4];
#pragma unroll
    for (int ti = 0; ti < 16; ti++)
#pragma unroll
        for (int q = 0; q < 4; q++) acc[ti][q] = 0.0f;

    int lr = l & 15;
    int lh = l >> 4;

    for (int kb = 0; kb < IN_DIM; kb += KC) {
        __syncthreads();   // previous iteration's ldmatrix reads done
        // ---- load A tile: 64 x 32 fp32 -> hi/lo fp16 ----
#pragma unroll
        for (int i = 0; i < 4; i++) {
            int lin = t + i * 128;       // float4 idx 0..511
            int r = lin >> 3;            // 8 float4 per row
            int c = lin & 7;
            int gr = block_m + r;
            float4 v = make_float4(0.f, 0.f, 0.f, 0.f);
            if (gr < N_NODES)
                v = ((const float4*)(h + (size_t)gr * IN_DIM + kb))[c];
            __half hx, lx, hy, ly, hz, lz, hw, lw;
            split_f32(v.x, hx, lx); split_f32(v.y, hy, ly);
            split_f32(v.z, hz, lz); split_f32(v.w, hw, lw);
            __half2 a0 = __halves2half2(hx, hy);
            __half2 a1 = __halves2half2(hz, hw);
            uint2 hi2; hi2.x = *(uint32_t*)&a0; hi2.y = *(uint32_t*)&a1;
            *(uint2*)&sa_hi[r * SA_STR + 4 * c] = hi2;
            __half2 b0 = __halves2half2(lx, ly);
            __half2 b1 = __halves2half2(lz, lw);
            uint2 lo2; lo2.x = *(uint32_t*)&b0; lo2.y = *(uint32_t*)&b1;
            *(uint2*)&sa_lo[r * SA_STR + 4 * c] = lo2;
        }
        // ---- load B tile: 32 x 128 halfs from presplit W ----
#pragma unroll
        for (int i = 0; i < 4; i++) {
            int lin = t + i * 128;       // uint4 idx 0..511 (8 halfs each)
            int r = lin >> 4;            // 16 uint4 per row
            int c = lin & 15;
            *(uint4*)&sb_hi[r * SB_STR + 8 * c] =
                *(const uint4*)&g_Whi[(size_t)(kb + r) * ODIM + 8 * c];
            *(uint4*)&sb_lo[r * SB_STR + 8 * c] =
                *(const uint4*)&g_Wlo[(size_t)(kb + r) * ODIM + 8 * c];
        }
        __syncthreads();

#pragma unroll
        for (int ks = 0; ks < KC; ks += 16) {
            uint32_t ah[4], al[4];
            uint32_t aaddr_h = s2u(&sa_hi[(16 * w + lr) * SA_STR + ks + 8 * lh]);
            uint32_t aaddr_l = s2u(&sa_lo[(16 * w + lr) * SA_STR + ks + 8 * lh]);
            LDMX4(ah[0], ah[1], ah[2], ah[3], aaddr_h);
            LDMX4(al[0], al[1], al[2], al[3], aaddr_l);
#pragma unroll
            for (int nt = 0; nt < 8; nt++) {   // pairs of n-tiles, n0 = 16*nt
                uint32_t bh[4], bl[4];
                uint32_t baddr_h = s2u(&sb_hi[(ks + lr) * SB_STR + 16 * nt + 8 * lh]);
                uint32_t baddr_l = s2u(&sb_lo[(ks + lr) * SB_STR + 16 * nt + 8 * lh]);
                LDMX4T(bh[0], bh[1], bh[2], bh[3], baddr_h);
                LDMX4T(bl[0], bl[1], bl[2], bl[3], baddr_l);
                MMA16816(acc[2 * nt],     ah, bh[0], bh[1]);
                MMA16816(acc[2 * nt],     al, bh[0], bh[1]);
                MMA16816(acc[2 * nt],     ah, bl[0], bl[1]);
                MMA16816(acc[2 * nt + 1], ah, bh[2], bh[3]);
                MMA16816(acc[2 * nt + 1], al, bh[2], bh[3]);
                MMA16816(acc[2 * nt + 1], ah, bl[2], bl[3]);
            }
        }
    }
    __syncthreads();   // mainloop reads done; reuse smem as fp32 staging

    // ---- stage accumulators to smem: st[64][133] ----
    {
        int g = l >> 2, q = l & 3;
#pragma unroll
        for (int ti = 0; ti < 16; ti++) {
            int c0 = 8 * ti + 2 * q;
            int r0 = 16 * w + g;
            st[r0 * ST_STR + c0]           = acc[ti][0];
            st[r0 * ST_STR + c0 + 1]       = acc[ti][1];
            st[(r0 + 8) * ST_STR + c0]     = acc[ti][2];
            st[(r0 + 8) * ST_STR + c0 + 1] = acc[ti][3];
        }
    }
    __syncthreads();

    // ---- alphas: one thread per row ----
    if (t < TM) {
        int n = block_m + t;
        if (n < N_NODES) {
            float vs[4] = {0.f, 0.f, 0.f, 0.f};
            float vd[4] = {0.f, 0.f, 0.f, 0.f};
#pragma unroll 4
            for (int c = 0; c < ODIM; c++) {
                float v = st[t * ST_STR + c];
                int hh = c >> 5;
                vs[hh] = fmaf(v, s_asc[c], vs[hh]);
                vd[hh] = fmaf(v, s_adc[c], vd[hh]);
            }
            g_alphas[n] = make_float4(vs[0], vs[1], vs[2], vs[3]);
            g_alphad[n] = make_float4(vd[0], vd[1], vd[2], vd[3]);
        }
    }

    // ---- fp16 h_prime store, coalesced ----
#pragma unroll
    for (int i = 0; i < 16; i++) {
        int lin = t + i * 128;           // uint2 idx 0..2047 (4 halfs each)
        int r = lin >> 5;                // 32 uint2 per row
        int q = lin & 31;
        int n = block_m + r;
        if (n < N_NODES) {
            __half2 p0 = __floats2half2_rn(st[r * ST_STR + 4 * q],
                                           st[r * ST_STR + 4 * q + 1]);
            __half2 p1 = __floats2half2_rn(st[r * ST_STR + 4 * q + 2],
                                           st[r * ST_STR + 4 * q + 3]);
            uint2 u; u.x = *(uint32_t*)&p0; u.y = *(uint32_t*)&p1;
            ((uint2*)g_hph)[(size_t)n * 32 + q] = u;
        }
    }
}

// ---------------- bucket scatter: 8 edges/thread, atomics batched for MLP ----------------
__global__ __launch_bounds__(256) void bucket_kernel(const int4* __restrict__ src4,
                                                     const int4* __restrict__ dst4) {
    int i = blockIdx.x * blockDim.x + threadIdx.x;
    if (i >= N_EDGES / 8) return;
    int4 s0 = src4[2 * i], s1 = src4[2 * i + 1];
    int4 d0 = dst4[2 * i], d1 = dst4[2 * i + 1];
    int ss[8] = {s0.x, s0.y, s0.z, s0.w, s1.x, s1.y, s1.z, s1.w};
    int dd[8] = {d0.x, d0.y, d0.z, d0.w, d1.x, d1.y, d1.z, d1.w};
    int pos[8];
#pragma unroll
    for (int q = 0; q < 8; q++)
        pos[q] = atomicAdd(&g_cursor[dd[q]], 1);     // 8 independent atomics in flight
#pragma unroll
    for (int q = 0; q < 8; q++)
        if (pos[q] < CAP) g_slots[(dd[q] << 7) + pos[q]] = ss[q];
}

// ---------------- aggregate: TWO nodes per warp, branch-free even loop + tail ----------------
// lane = 16*half + hl; lane owns cols 8*hl..8*hl+7 (one uint4 of fp16), head = hl>>2.
__global__ __launch_bounds__(256, 6) void agg_kernel(float4* __restrict__ out4) {
    int warp_id = (blockIdx.x * blockDim.x + threadIdx.x) >> 5;
    int lane = threadIdx.x & 31;
    int half = lane >> 4;
    int hl = lane & 15;
    int node = warp_id * 2 + half;          // N_NODES even: both halves valid or both out
    if (node >= N_NODES) return;
    int head = hl >> 2;

    int cnt = g_cursor[node];
    if (cnt > CAP) cnt = CAP;
    int beg = node << 7;

    float ad = ((const float*)&g_alphad[node])[head];
    const float* alph = (const float*)g_alphas;
    const uint4* hp4 = (const uint4*)g_hph;   // 16 uint4 per node row

    float4 accA = make_float4(0.f, 0.f, 0.f, 0.f);
    float4 accB = make_float4(0.f, 0.f, 0.f, 0.f);
    float ssum = 0.0f;

    int cnt2 = cnt & ~1;
    for (int j = 0; j < cnt2; j += 2) {
        int2 s2 = *(const int2*)&g_slots[beg + j];   // 8B-aligned: beg%128==0, j%2==0

        // independent gathers first (MLP)
        float as0 = alph[4 * s2.x + head];
        float as1 = alph[4 * s2.y + head];
        uint4 v0 = hp4[(size_t)s2.x * 16 + hl];
        uint4 v1 = hp4[(size_t)s2.y * 16 + hl];

        float att0 = as0 + ad; att0 = fmaxf(att0, ALPHA * att0);
        float att1 = as1 + ad; att1 = fmaxf(att1, ALPHA * att1);
        float e0 = __expf(att0);
        float e1 = __expf(att1);
        ssum += e0 + e1;

        float2 f;
        f = __half22float2(*(const __half2*)&v0.x);
        accA.x = fmaf(e0, f.x, accA.x); accA.y = fmaf(e0, f.y, accA.y);
        f = __half22float2(*(const __half2*)&v0.y);
        accA.z = fmaf(e0, f.x, accA.z); accA.w = fmaf(e0, f.y, accA.w);
        f = __half22float2(*(const __half2*)&v0.z);
        accB.x = fmaf(e0, f.x, accB.x); accB.y = fmaf(e0, f.y, accB.y);
        f = __half22float2(*(const __half2*)&v0.w);
        accB.z = fmaf(e0, f.x, accB.z); accB.w = fmaf(e0, f.y, accB.w);

        f = __half22float2(*(const __half2*)&v1.x);
        accA.x = fmaf(e1, f.x, accA.x); accA.y = fmaf(e1, f.y, accA.y);
        f = __half22float2(*(const __half2*)&v1.y);
        accA.z = fmaf(e1, f.x, accA.z); accA.w = fmaf(e1, f.y, accA.w);
        f = __half22float2(*(const __half2*)&v1.z);
        accB.x = fmaf(e1, f.x, accB.x); accB.y = fmaf(e1, f.y, accB.y);
        f = __half22float2(*(const __half2*)&v1.w);
        accB.z = fmaf(e1, f.x, accB.z); accB.w = fmaf(e1, f.y, accB.w);
    }
    if (cnt & 1) {
        int s = g_slots[beg + cnt2];
        float as = alph[4 * s + head];
        uint4 v = hp4[(size_t)s * 16 + hl];
        float att = as + ad; att = fmaxf(att, ALPHA * att);
        float e = __expf(att);
        ssum += e;
        float2 f;
        f = __half22float2(*(const __half2*)&v.x);
        accA.x = fmaf(e, f.x, accA.x); accA.y = fmaf(e, f.y, accA.y);
        f = __half22float2(*(const __half2*)&v.y);
        accA.z = fmaf(e, f.x, accA.z); accA.w = fmaf(e, f.y, accA.w);
        f = __half22float2(*(const __half2*)&v.z);
        accB.x = fmaf(e, f.x, accB.x); accB.y = fmaf(e, f.y, accB.y);
        f = __half22float2(*(const __half2*)&v.w);
        accB.z = fmaf(e, f.x, accB.z); accB.w = fmaf(e, f.y, accB.w);
    }

    float inv = (cnt > 0) ? 1.0f / ssum : 0.0f;
    size_t ob = (size_t)node * 32 + 2 * hl;
    out4[ob]     = make_float4(accA.x * inv, accA.y * inv, accA.z * inv, accA.w * inv);
    out4[ob + 1] = make_float4(accB.x * inv, accB.y * inv, accB.z * inv, accB.w * inv);

    if (hl == 0) g_cursor[node] = 0;   // restore for next graph replay
}

// ---------------- launch ----------------
extern "C" void kernel_launch(void* const* d_in, const int* in_sizes, int n_in,
                              void* d_out, int out_size) {
    const float* h   = (const float*)d_in[0];
    const int*   adj = (const int*)d_in[1];
    const float* W   = (const float*)d_in[2];
    const float* a   = (const float*)d_in[3];

    const int* src = adj;
    const int* dst = adj + N_EDGES;

    static cudaStream_t s2 = nullptr;
    static cudaEvent_t evA = nullptr, evB = nullptr;
    if (!s2) {
        cudaStreamCreateWithFlags(&s2, cudaStreamNonBlocking);
        cudaEventCreateWithFlags(&evA, cudaEventDisableTiming);
        cudaEventCreateWithFlags(&evB, cudaEventDisableTiming);
    }

    cudaEventRecord(evA, 0);
    cudaStreamWaitEvent(s2, evA, 0);

    bucket_kernel<<<(N_EDGES / 8 + 255) / 256, 256, 0, s2>>>((const int4*)src,
                                                             (const int4*)dst);
    cudaEventRecord(evB, s2);

    wsplit_kernel<<<(IN_DIM * ODIM + 255) / 256, 256>>>(W);
    gemm_kernel<<<(N_NODES + TM - 1) / TM, 128>>>(h, a);

    cudaStreamWaitEvent(0, evB, 0);
    // two nodes per warp -> 8 warps per 256-thread block handle 16 nodes
    agg_kernel<<<(N_NODES / 2 + 7) / 8, 256>>>((float4*)d_out);
}

// round 16
// speedup vs baseline: 1.0295x; 1.0295x over previous
#include <cuda_runtime.h>
#include <cuda_fp16.h>
#include <cstdint>

#define N_NODES 50000
#define N_EDGES 1600000
#define IN_DIM 256
#define OUT_DIM 32
#define NH 4
#define ODIM 128   // NH*OUT_DIM
#define ALPHA 0.2f
#define CAP 128    // slots per node; P(deg>=128) ~ e^-41 per node (Poisson, mean 32)

// ---------------- scratch (no allocations allowed) ----------------
__device__ __half g_hph[N_NODES * ODIM];     // h_prime in fp16 (12.8 MB)
__device__ float4 g_alphas[N_NODES];         // alpha_src per node, 4 heads
__device__ float4 g_alphad[N_NODES];         // alpha_dst per node, 4 heads
__device__ int    g_cursor[N_NODES];         // bucket fill counters (agg resets -> replay-safe)
__device__ int    g_slots[N_NODES * CAP];    // per-dst src buckets (25.6 MB)
__device__ __half g_Whi[IN_DIM * ODIM];      // fp16 split of W (hi)
__device__ __half g_Wlo[IN_DIM * ODIM];      // fp16 split of W (lo)

// ---------------- W split: W = Whi + Wlo (fp16 pair) ----------------
__global__ __launch_bounds__(256) void wsplit_kernel(const float* __restrict__ W) {
    int i = blockIdx.x * blockDim.x + threadIdx.x;
    if (i < IN_DIM * ODIM) {
        float w = W[i];
        __half hi = __float2half(w);
        g_Whi[i] = hi;
        g_Wlo[i] = __float2half(w - __half2float(hi));
    }
}

// ---------------- MMA helpers ----------------
__device__ __forceinline__ uint32_t s2u(const void* p) {
    return (uint32_t)__cvta_generic_to_shared(p);
}
#define LDMX4(r0, r1, r2, r3, addr) \
    asm volatile("ldmatrix.sync.aligned.m8n8.x4.shared.b16 {%0,%1,%2,%3}, [%4];" \
                 : "=r"(r0), "=r"(r1), "=r"(r2), "=r"(r3) : "r"(addr))
#define LDMX4T(r0, r1, r2, r3, addr) \
    asm volatile("ldmatrix.sync.aligned.m8n8.x4.trans.shared.b16 {%0,%1,%2,%3}, [%4];" \
                 : "=r"(r0), "=r"(r1), "=r"(r2), "=r"(r3) : "r"(addr))
#define MMA16816(c, a, b0, b1) \
    asm volatile("mma.sync.aligned.m16n8k16.row.col.f32.f16.f16.f32 " \
                 "{%0,%1,%2,%3}, {%4,%5,%6,%7}, {%8,%9}, {%0,%1,%2,%3};" \
                 : "+f"((c)[0]), "+f"((c)[1]), "+f"((c)[2]), "+f"((c)[3]) \
                 : "r"((a)[0]), "r"((a)[1]), "r"((a)[2]), "r"((a)[3]), \
                   "r"(b0), "r"(b1))

// ---------------- GEMM: split-fp16 HMMA, 64 rows x 128 cols per block ----------------
#define TM 64
#define KC 32
#define SA_STR 40    // A smem row stride (halfs): conflict-free ldmatrix
#define SB_STR 136   // B smem row stride (halfs): conflict-free ldmatrix
#define ST_STR 133   // fp32 staging stride: gcd(133,32)=1

__global__ __launch_bounds__(128) void gemm_kernel(const float* __restrict__ h,
                                                   const float* __restrict__ a) {
    __shared__ __align__(16) unsigned char smem_raw[64 * ST_STR * 4];  // 34048 B
    __shared__ float s_asc[ODIM], s_adc[ODIM];

    __half* sa_hi = (__half*)smem_raw;                       // 64*40 halfs
    __half* sa_lo = sa_hi + TM * SA_STR;
    __half* sb_hi = (__half*)(smem_raw + 2 * TM * SA_STR * 2);
    __half* sb_lo = sb_hi + KC * SB_STR;
    float*  st    = (float*)smem_raw;                        // reused after mainloop

    int t = threadIdx.x;
    int w = t >> 5;
    int l = t & 31;
    int block_m = blockIdx.x * TM;

    if (t < ODIM) {
        s_asc[t] = a[(t & 31) * 4 + (t >> 5)];
        s_adc[t] = a[((t & 31) + 32) * 4 + (t >> 5)];
    }

    float acc[16][4];
#pragma unroll
    for (int ti = 0; ti < 16; ti++)
#pragma unroll
        for (int q = 0; q < 4; q++) acc[ti][q] = 0.0f;

    int lr = l & 15;
    int lh = l >> 4;

    for (int kb = 0; kb < IN_DIM; kb += KC) {
        __syncthreads();   // previous iteration's ldmatrix reads done
        // ---- load A tile: 64 x 32 fp32 -> hi/lo fp16 via packed cvt.f16x2.f32 ----
#pragma unroll
        for (int i = 0; i < 4; i++) {
            int lin = t + i * 128;       // float4 idx 0..511
            int r = lin >> 3;            // 8 float4 per row
            int c = lin & 7;
            int gr = block_m + r;
            float4 v = make_float4(0.f, 0.f, 0.f, 0.f);
            if (gr < N_NODES)
                v = ((const float4*)(h + (size_t)gr * IN_DIM + kb))[c];
            // packed hi conversion: 1 instr per float pair
            __half2 h01 = __floats2half2_rn(v.x, v.y);
            __half2 h23 = __floats2half2_rn(v.z, v.w);
            float2 c01 = __half22float2(h01);
            float2 c23 = __half22float2(h23);
            __half2 l01 = __floats2half2_rn(v.x - c01.x, v.y - c01.y);
            __half2 l23 = __floats2half2_rn(v.z - c23.x, v.w - c23.y);
            uint2 hi2; hi2.x = *(uint32_t*)&h01; hi2.y = *(uint32_t*)&h23;
            *(uint2*)&sa_hi[r * SA_STR + 4 * c] = hi2;
            uint2 lo2; lo2.x = *(uint32_t*)&l01; lo2.y = *(uint32_t*)&l23;
            *(uint2*)&sa_lo[r * SA_STR + 4 * c] = lo2;
        }
        // ---- load B tile: 32 x 128 halfs from presplit W ----
#pragma unroll
        for (int i = 0; i < 4; i++) {
            int lin = t + i * 128;       // uint4 idx 0..511 (8 halfs each)
            int r = lin >> 4;            // 16 uint4 per row
            int c = lin & 15;
            *(uint4*)&sb_hi[r * SB_STR + 8 * c] =
                *(const uint4*)&g_Whi[(size_t)(kb + r) * ODIM + 8 * c];
            *(uint4*)&sb_lo[r * SB_STR + 8 * c] =
                *(const uint4*)&g_Wlo[(size_t)(kb + r) * ODIM + 8 * c];
        }
        __syncthreads();

#pragma unroll
        for (int ks = 0; ks < KC; ks += 16) {
            uint32_t ah[4], al[4];
            uint32_t aaddr_h = s2u(&sa_hi[(16 * w + lr) * SA_STR + ks + 8 * lh]);
            uint32_t aaddr_l = s2u(&sa_lo[(16 * w + lr) * SA_STR + ks + 8 * lh]);
            LDMX4(ah[0], ah[1], ah[2], ah[3], aaddr_h);
            LDMX4(al[0], al[1], al[2], al[3], aaddr_l);
#pragma unroll
            for (int nt = 0; nt < 8; nt++) {   // pairs of n-tiles, n0 = 16*nt
                uint32_t bh[4], bl[4];
                uint32_t baddr_h = s2u(&sb_hi[(ks + lr) * SB_STR + 16 * nt + 8 * lh]);
                uint32_t baddr_l = s2u(&sb_lo[(ks + lr) * SB_STR + 16 * nt + 8 * lh]);
                LDMX4T(bh[0], bh[1], bh[2], bh[3], baddr_h);
                LDMX4T(bl[0], bl[1], bl[2], bl[3], baddr_l);
                MMA16816(acc[2 * nt],     ah, bh[0], bh[1]);
                MMA16816(acc[2 * nt],     al, bh[0], bh[1]);
                MMA16816(acc[2 * nt],     ah, bl[0], bl[1]);
                MMA16816(acc[2 * nt + 1], ah, bh[2], bh[3]);
                MMA16816(acc[2 * nt + 1], al, bh[2], bh[3]);
                MMA16816(acc[2 * nt + 1], ah, bl[2], bl[3]);
            }
        }
    }
    __syncthreads();   // mainloop reads done; reuse smem as fp32 staging

    // ---- stage accumulators to smem: st[64][133] ----
    {
        int g = l >> 2, q = l & 3;
#pragma unroll
        for (int ti = 0; ti < 16; ti++) {
            int c0 = 8 * ti + 2 * q;
            int r0 = 16 * w + g;
            st[r0 * ST_STR + c0]           = acc[ti][0];
            st[r0 * ST_STR + c0 + 1]       = acc[ti][1];
            st[(r0 + 8) * ST_STR + c0]     = acc[ti][2];
            st[(r0 + 8) * ST_STR + c0 + 1] = acc[ti][3];
        }
    }
    __syncthreads();

    // ---- alphas: one thread per row ----
    if (t < TM) {
        int n = block_m + t;
        if (n < N_NODES) {
            float vs[4] = {0.f, 0.f, 0.f, 0.f};
            float vd[4] = {0.f, 0.f, 0.f, 0.f};
#pragma unroll 4
            for (int c = 0; c < ODIM; c++) {
                float v = st[t * ST_STR + c];
                int hh = c >> 5;
                vs[hh] = fmaf(v, s_asc[c], vs[hh]);
                vd[hh] = fmaf(v, s_adc[c], vd[hh]);
            }
            g_alphas[n] = make_float4(vs[0], vs[1], vs[2], vs[3]);
            g_alphad[n] = make_float4(vd[0], vd[1], vd[2], vd[3]);
        }
    }

    // ---- fp16 h_prime store, coalesced ----
#pragma unroll
    for (int i = 0; i < 16; i++) {
        int lin = t + i * 128;           // uint2 idx 0..2047 (4 halfs each)
        int r = lin >> 5;                // 32 uint2 per row
        int q = lin & 31;
        int n = block_m + r;
        if (n < N_NODES) {
            __half2 p0 = __floats2half2_rn(st[r * ST_STR + 4 * q],
                                           st[r * ST_STR + 4 * q + 1]);
            __half2 p1 = __floats2half2_rn(st[r * ST_STR + 4 * q + 2],
                                           st[r * ST_STR + 4 * q + 3]);
            uint2 u; u.x = *(uint32_t*)&p0; u.y = *(uint32_t*)&p1;
            ((uint2*)g_hph)[(size_t)n * 32 + q] = u;
        }
    }
}

// ---------------- bucket scatter: 4 edges/thread (measured-good r14 form) ----------------
__global__ __launch_bounds__(256) void bucket_kernel(const int4* __restrict__ src4,
                                                     const int4* __restrict__ dst4) {
    int i = blockIdx.x * blockDim.x + threadIdx.x;
    if (i >= N_EDGES / 4) return;
    int4 s = src4[i];
    int4 d = dst4[i];
#pragma unroll
    for (int q = 0; q < 4; q++) {
        int dd = (&d.x)[q];
        int ss = (&s.x)[q];
        int pos = atomicAdd(&g_cursor[dd], 1);
        if (pos < CAP) g_slots[(dd << 7) + pos] = ss;
    }
}

// ---------------- aggregate: TWO nodes per warp, branch-free even loop + tail ----------------
// lane = 16*half + hl; lane owns cols 8*hl..8*hl+7 (one uint4 of fp16), head = hl>>2.
__global__ __launch_bounds__(256, 6) void agg_kernel(float4* __restrict__ out4) {
    int warp_id = (blockIdx.x * blockDim.x + threadIdx.x) >> 5;
    int lane = threadIdx.x & 31;
    int half = lane >> 4;
    int hl = lane & 15;
    int node = warp_id * 2 + half;          // N_NODES even: both halves valid or both out
    if (node >= N_NODES) return;
    int head = hl >> 2;

    int cnt = g_cursor[node];
    if (cnt > CAP) cnt = CAP;
    int beg = node << 7;

    float ad = ((const float*)&g_alphad[node])[head];
    const float* alph = (const float*)g_alphas;
    const uint4* hp4 = (const uint4*)g_hph;   // 16 uint4 per node row

    float4 accA = make_float4(0.f, 0.f, 0.f, 0.f);
    float4 accB = make_float4(0.f, 0.f, 0.f, 0.f);
    float ssum = 0.0f;

    int cnt2 = cnt & ~1;
    for (int j = 0; j < cnt2; j += 2) {
        int2 s2 = *(const int2*)&g_slots[beg + j];   // 8B-aligned: beg%128==0, j%2==0

        // independent gathers first (MLP)
        float as0 = alph[4 * s2.x + head];
        float as1 = alph[4 * s2.y + head];
        uint4 v0 = hp4[(size_t)s2.x * 16 + hl];
        uint4 v1 = hp4[(size_t)s2.y * 16 + hl];

        float att0 = as0 + ad; att0 = fmaxf(att0, ALPHA * att0);
        float att1 = as1 + ad; att1 = fmaxf(att1, ALPHA * att1);
        float e0 = __expf(att0);
        float e1 = __expf(att1);
        ssum += e0 + e1;

        float2 f;
        f = __half22float2(*(const __half2*)&v0.x);
        accA.x = fmaf(e0, f.x, accA.x); accA.y = fmaf(e0, f.y, accA.y);
        f = __half22float2(*(const __half2*)&v0.y);
        accA.z = fmaf(e0, f.x, accA.z); accA.w = fmaf(e0, f.y, accA.w);
        f = __half22float2(*(const __half2*)&v0.z);
        accB.x = fmaf(e0, f.x, accB.x); accB.y = fmaf(e0, f.y, accB.y);
        f = __half22float2(*(const __half2*)&v0.w);
        accB.z = fmaf(e0, f.x, accB.z); accB.w = fmaf(e0, f.y, accB.w);

        f = __half22float2(*(const __half2*)&v1.x);
        accA.x = fmaf(e1, f.x, accA.x); accA.y = fmaf(e1, f.y, accA.y);
        f = __half22float2(*(const __half2*)&v1.y);
        accA.z = fmaf(e1, f.x, accA.z); accA.w = fmaf(e1, f.y, accA.w);
        f = __half22float2(*(const __half2*)&v1.z);
        accB.x = fmaf(e1, f.x, accB.x); accB.y = fmaf(e1, f.y, accB.y);
        f = __half22float2(*(const __half2*)&v1.w);
        accB.z = fmaf(e1, f.x, accB.z); accB.w = fmaf(e1, f.y, accB.w);
    }
    if (cnt & 1) {
        int s = g_slots[beg + cnt2];
        float as = alph[4 * s + head];
        uint4 v = hp4[(size_t)s * 16 + hl];
        float att = as + ad; att = fmaxf(att, ALPHA * att);
        float e = __expf(att);
        ssum += e;
        float2 f;
        f = __half22float2(*(const __half2*)&v.x);
        accA.x = fmaf(e, f.x, accA.x); accA.y = fmaf(e, f.y, accA.y);
        f = __half22float2(*(const __half2*)&v.y);
        accA.z = fmaf(e, f.x, accA.z); accA.w = fmaf(e, f.y, accA.w);
        f = __half22float2(*(const __half2*)&v.z);
        accB.x = fmaf(e, f.x, accB.x); accB.y = fmaf(e, f.y, accB.y);
        f = __half22float2(*(const __half2*)&v.w);
        accB.z = fmaf(e, f.x, accB.z); accB.w = fmaf(e, f.y, accB.w);
    }

    float inv = (cnt > 0) ? 1.0f / ssum : 0.0f;
    size_t ob = (size_t)node * 32 + 2 * hl;
    out4[ob]     = make_float4(accA.x * inv, accA.y * inv, accA.z * inv, accA.w * inv);
    out4[ob + 1] = make_float4(accB.x * inv, accB.y * inv, accB.z * inv, accB.w * inv);

    if (hl == 0) g_cursor[node] = 0;   // restore for next graph replay
}

// ---------------- launch: fork bucket scatter alongside W-split + GEMM ----------------
extern "C" void kernel_launch(void* const* d_in, const int* in_sizes, int n_in,
                              void* d_out, int out_size) {
    const float* h   = (const float*)d_in[0];
    const int*   adj = (const int*)d_in[1];
    const float* W   = (const float*)d_in[2];
    const float* a   = (const float*)d_in[3];

    const int* src = adj;
    const int* dst = adj + N_EDGES;

    static cudaStream_t s2 = nullptr;
    static cudaEvent_t evA = nullptr, evB = nullptr;
    if (!s2) {
        cudaStreamCreateWithFlags(&s2, cudaStreamNonBlocking);
        cudaEventCreateWithFlags(&evA, cudaEventDisableTiming);
        cudaEventCreateWithFlags(&evB, cudaEventDisableTiming);
    }

    cudaEventRecord(evA, 0);
    cudaStreamWaitEvent(s2, evA, 0);

    bucket_kernel<<<(N_EDGES / 4 + 255) / 256, 256, 0, s2>>>((const int4*)src,
                                                             (const int4*)dst);
    cudaEventRecord(evB, s2);

    wsplit_kernel<<<(IN_DIM * ODIM + 255) / 256, 256>>>(W);
    gemm_kernel<<<(N_NODES + TM - 1) / TM, 128>>>(h, a);

    cudaStreamWaitEvent(0, evB, 0);
    // two nodes per warp -> 8 warps per 256-thread block handle 16 nodes
    agg_kernel<<<(N_NODES / 2 + 7) / 8, 256>>>((float4*)d_out);
}